// round 15
// baseline (speedup 1.0000x reference)
#include <cuda_runtime.h>
#include <cuda_bf16.h>
#include <cstdint>

#define M_TOT   8192
#define K_IN    4096
#define RANK    256
#define N_OUT   4096
#define VERA_SCALE (32.0f / 256.0f)

// pre-split bf16 hi/lo planes (packed 2 elems per uint32, row-major)
__device__ uint32_t g_Ahi[(size_t)RANK * K_IN / 2];
__device__ uint32_t g_Alo[(size_t)RANK * K_IN / 2];
__device__ uint32_t g_Bhi[(size_t)N_OUT * RANK / 2];
__device__ uint32_t g_Blo[(size_t)N_OUT * RANK / 2];
// split-K partials for GEMM1 and the split intermediate t
__device__ float    g_p[2][(size_t)M_TOT * RANK];
__device__ uint32_t g_thi[(size_t)M_TOT * RANK / 2];
__device__ uint32_t g_tlo[(size_t)M_TOT * RANK / 2];

// ------------- helpers -------------
__device__ __forceinline__ uint32_t smem_u32(const void* p) {
    uint32_t a;
    asm("{ .reg .u64 t; cvta.to.shared.u64 t, %1; cvt.u32.u64 %0, t; }" : "=r"(a) : "l"(p));
    return a;
}
__device__ __forceinline__ void ldsm4(uint32_t r[4], uint32_t addr) {
    asm volatile("ldmatrix.sync.aligned.m8n8.x4.shared.b16 {%0,%1,%2,%3}, [%4];"
                 : "=r"(r[0]), "=r"(r[1]), "=r"(r[2]), "=r"(r[3]) : "r"(addr));
}
__device__ __forceinline__ void mma_bf16(float c[4], const uint32_t a[4],
                                         uint32_t b0, uint32_t b1) {
    asm volatile(
        "mma.sync.aligned.m16n8k16.row.col.f32.bf16.bf16.f32 "
        "{%0,%1,%2,%3}, {%4,%5,%6,%7}, {%8,%9}, {%0,%1,%2,%3};"
        : "+f"(c[0]), "+f"(c[1]), "+f"(c[2]), "+f"(c[3])
        : "r"(a[0]), "r"(a[1]), "r"(a[2]), "r"(a[3]), "r"(b0), "r"(b1));
}
__device__ __forceinline__ uint32_t sw128(uint32_t b) {
    return b ^ ((b >> 3) & 0x70);
}
__device__ __forceinline__ void split2(float a, float b, uint32_t& hi, uint32_t& lo) {
    uint32_t ua = __float_as_uint(a), ub = __float_as_uint(b);
    hi = __byte_perm(ua, ub, 0x7632);
    float fa = __uint_as_float(ua & 0xFFFF0000u);
    float fb = __uint_as_float(ub & 0xFFFF0000u);
    float la = a - fa, lb = b - fb;
    asm("cvt.rn.bf16x2.f32 %0, %1, %2;" : "=r"(lo) : "f"(lb), "f"(la));
}
__device__ __forceinline__ void cpa16(uint32_t dst, const void* src) {
    asm volatile("cp.async.cg.shared.global [%0], [%1], 16;" :: "r"(dst), "l"(src));
}
#define CP_COMMIT() asm volatile("cp.async.commit_group;" ::: "memory")
#define CP_WAIT0()  asm volatile("cp.async.wait_group 0;" ::: "memory")

// one-shot pre-split: fp32 matrix -> planar packed-bf16 hi/lo
__global__ void split_kernel(const float4* __restrict__ in, uint32_t* __restrict__ hi,
                             uint32_t* __restrict__ lo, int n4) {
    int i = blockIdx.x * blockDim.x + threadIdx.x;
    if (i < n4) {
        float4 v = in[i];
        uint32_t h0, l0, h1, l1;
        split2(v.x, v.y, h0, l0);
        split2(v.z, v.w, h1, l1);
        hi[2 * i] = h0; hi[2 * i + 1] = h1;
        lo[2 * i] = l0; lo[2 * i + 1] = l1;
    }
}

// combine split-K partials, scale by d_A, emit split hi/lo t
__global__ void combine_kernel(const float* __restrict__ p0, const float* __restrict__ p1,
                               const float* __restrict__ dA,
                               uint32_t* __restrict__ thi, uint32_t* __restrict__ tlo,
                               int n4) {
    int i = blockIdx.x * blockDim.x + threadIdx.x;
    if (i < n4) {
        float4 a = reinterpret_cast<const float4*>(p0)[i];
        float4 b = reinterpret_cast<const float4*>(p1)[i];
        int col = (i * 4) & (RANK - 1);
        float4 s = *reinterpret_cast<const float4*>(dA + col);
        uint32_t h, l;
        split2((a.x + b.x) * s.x, (a.y + b.y) * s.y, h, l);
        thi[2 * i] = h; tlo[2 * i] = l;
        split2((a.z + b.z) * s.z, (a.w + b.w) * s.w, h, l);
        thi[2 * i + 1] = h; tlo[2 * i + 1] = l;
    }
}

// ============ GEMM1: partial = X @ A^T (split-K=2), X fp32 staged via cp.async
// CTA 64(m) x 256(n), grid (128 m-tiles, 2 splits) = 256 CTAs. 256 threads =
// 8 warps (2m x 4n), warp tile 32x64. Each K-chunk (64): cp.async fp32 X tile
// into padded SMEM, all threads convert (LDS->split2->STS), then MMA. A-side
// pre-split bf16 via cp.async. Double-buffered f32/A stages, single bf16X buf.
__global__ __launch_bounds__(256, 1)
void vera_g1(const float* __restrict__ X,
             const uint32_t* __restrict__ Ahi_, const uint32_t* __restrict__ Alo_,
             float* __restrict__ Part)
{
    extern __shared__ char smem[];
    constexpr int F32STRIDE = 272;              // 64 floats + 16B pad (bank spread)
    constexpr int F32SZ = 64 * F32STRIDE;       // 17408 per stage
    constexpr int XHI = 2 * F32SZ;              // 34816
    constexpr int XLO = XHI + 8192;             // 43008
    constexpr int APL = XLO + 8192;             // 51200
    constexpr int APLANE = 32768;
    constexpr int ASTG = 2 * APLANE;            // 65536 per stage
    constexpr int NC = 32;                      // chunks of 64 (K=2048 per split)
    const uint32_t sb = smem_u32(smem);

    const int tid = threadIdx.x, wid = tid >> 5, lid = tid & 31;
    const int bm = blockIdx.x * 64;
    const int split = blockIdx.y;
    const int koff_u32 = split * 1024;
    const int koff_el  = split * 2048;
    const int Ku2 = K_IN / 2;
    float* Out = Part + (size_t)split * M_TOT * RANK;

    // consumer addressing (warp tile 32x64)
    const int warp_m = wid & 1, warp_n = wid >> 1;
    const int rowA = warp_m * 32 + (lid & 15);
    const uint32_t pA0 = (uint32_t)(rowA * 128), pA1 = pA0 + 2048;
    const uint32_t kbA = (uint32_t)((lid >> 4) * 16);
    const uint32_t xA  = (uint32_t)((rowA & 7) << 4);
    const int rowB = warp_n * 64 + ((lid >> 4) * 8 + (lid & 7));
    const uint32_t pB0 = (uint32_t)(rowB * 128);
    const uint32_t kbB = (uint32_t)(((lid >> 3) & 1) * 16);
    const uint32_t xB  = (uint32_t)((rowB & 7) << 4);

    // X staging/convert addressing: thread -> (row, 16-float column block)
    const int xrow = tid >> 2, xc = tid & 3;

    float acc[2][8][4];
    #pragma unroll
    for (int i = 0; i < 2; ++i)
        #pragma unroll
        for (int j = 0; j < 8; ++j)
            #pragma unroll
            for (int q = 0; q < 4; ++q) acc[i][j][q] = 0.0f;

    // --- fill helpers ---
    auto fillA = [&](int stg, int ch) {
        const int col = koff_u32 + ch * 32;
        const uint32_t d = sb + (uint32_t)(APL + stg * ASTG);
        #pragma unroll
        for (int j = 0; j < 8; ++j) {
            uint32_t off = sw128((uint32_t)(tid * 128 + j * 16));
            cpa16(d + off,          Ahi_ + (size_t)tid * Ku2 + col + j * 4);
            cpa16(d + APLANE + off, Alo_ + (size_t)tid * Ku2 + col + j * 4);
        }
    };
    auto fillX = [&](int stg, int ch) {
        const float* src = X + (size_t)(bm + xrow) * K_IN + koff_el + ch * 64 + xc * 16;
        const uint32_t d = sb + (uint32_t)(stg * F32SZ + xrow * F32STRIDE + xc * 64);
        #pragma unroll
        for (int j = 0; j < 4; ++j)
            cpa16(d + (uint32_t)(j * 16), src + j * 4);
    };
    auto cvtX = [&](int stg) {
        const char* s = smem + stg * F32SZ + xrow * F32STRIDE + xc * 64;
        #pragma unroll
        for (int j = 0; j < 4; ++j) {
            float4 v = *reinterpret_cast<const float4*>(s + j * 16);
            uint32_t h0, l0, h1, l1;
            split2(v.x, v.y, h0, l0);
            split2(v.z, v.w, h1, l1);
            uint32_t off = sw128((uint32_t)(xrow * 128 + (xc * 4 + j) * 8));
            *reinterpret_cast<uint2*>(smem + XHI + off) = make_uint2(h0, h1);
            *reinterpret_cast<uint2*>(smem + XLO + off) = make_uint2(l0, l1);
        }
    };

    // prologue: stage 0
    fillX(0, 0); fillA(0, 0);
    CP_COMMIT(); CP_WAIT0();
    __syncthreads();

    for (int ch = 0; ch < NC; ++ch) {
        const int st = ch & 1;

        cvtX(st);                 // f32(ch) -> bf16 X planes
        __syncthreads();          // bf16X visible before ldsm

        if (ch + 1 < NC) { fillX(st ^ 1, ch + 1); fillA(st ^ 1, ch + 1); }
        CP_COMMIT();

        // MMA phase on bf16X + A[st]
        const uint32_t abase = sb + (uint32_t)(APL + st * ASTG);
        #pragma unroll
        for (int s = 0; s < 4; ++s) {
            const uint32_t aoff = ((uint32_t)(s * 32) + kbA) ^ xA;
            const uint32_t boff = ((uint32_t)(s * 32) + kbB) ^ xB;
            uint32_t ah[2][4], al[2][4];
            ldsm4(ah[0], sb + XHI + pA0 + aoff);
            ldsm4(ah[1], sb + XHI + pA1 + aoff);
            ldsm4(al[0], sb + XLO + pA0 + aoff);
            ldsm4(al[1], sb + XLO + pA1 + aoff);
            #pragma unroll
            for (int g = 0; g < 2; ++g) {
                uint32_t bh[2][4], bl[2][4];
                const uint32_t nb = abase + pB0 + boff + (uint32_t)(g * 4096);
                ldsm4(bh[0], nb);
                ldsm4(bh[1], nb + 2048);
                ldsm4(bl[0], nb + APLANE);
                ldsm4(bl[1], nb + APLANE + 2048);
                #pragma unroll
                for (int np = 0; np < 2; ++np)
                    #pragma unroll
                    for (int mi = 0; mi < 2; ++mi) {
                        const int j = (g * 2 + np) * 2;
                        mma_bf16(acc[mi][j],     ah[mi], bh[np][0], bh[np][1]);
                        mma_bf16(acc[mi][j + 1], ah[mi], bh[np][2], bh[np][3]);
                    }
                #pragma unroll
                for (int np = 0; np < 2; ++np)
                    #pragma unroll
                    for (int mi = 0; mi < 2; ++mi) {
                        const int j = (g * 2 + np) * 2;
                        mma_bf16(acc[mi][j],     ah[mi], bl[np][0], bl[np][1]);
                        mma_bf16(acc[mi][j + 1], ah[mi], bl[np][2], bl[np][3]);
                    }
                #pragma unroll
                for (int np = 0; np < 2; ++np)
                    #pragma unroll
                    for (int mi = 0; mi < 2; ++mi) {
                        const int j = (g * 2 + np) * 2;
                        mma_bf16(acc[mi][j],     al[mi], bh[np][0], bh[np][1]);
                        mma_bf16(acc[mi][j + 1], al[mi], bh[np][2], bh[np][3]);
                    }
            }
        }
        CP_WAIT0();
        __syncthreads();
    }

    // epilogue: raw fp32 partials (d_A applied in combine)
    const int mrow0 = bm + warp_m * 32 + (lid >> 2);
    const int nc0   = warp_n * 64 + (lid & 3) * 2;
    #pragma unroll
    for (int mi = 0; mi < 2; ++mi) {
        #pragma unroll
        for (int nj = 0; nj < 8; ++nj) {
            const int n = nc0 + nj * 8;
            const int m0 = mrow0 + mi * 16;
            *reinterpret_cast<float2*>(Out + (size_t)m0 * RANK + n) =
                make_float2(acc[mi][nj][0], acc[mi][nj][1]);
            *reinterpret_cast<float2*>(Out + (size_t)(m0 + 8) * RANK + n) =
                make_float2(acc[mi][nj][2], acc[mi][nj][3]);
        }
    }
}

// ============ GEMM2 (verbatim R11/R14 engine, measured 130us) ============
__global__ __launch_bounds__(512, 1)
void vera_g2(const uint32_t* __restrict__ Thi_, const uint32_t* __restrict__ Tlo_,
             const uint32_t* __restrict__ Bhi_, const uint32_t* __restrict__ Blo_,
             const float* __restrict__ dB, float* __restrict__ Out)
{
    extern __shared__ char smem[];
    constexpr int AP = 16384, BP = 32768;
    constexpr int STAGE = 2 * AP + 2 * BP;   // 96KB
    float* cs = reinterpret_cast<float*>(smem + 2 * STAGE);
    const uint32_t sb = smem_u32(smem);

    const int tid = threadIdx.x, wid = tid >> 5, lid = tid & 31;
    const int warp_m = wid & 3, warp_n = wid >> 2;
    const int bm = blockIdx.x * 128, bn = blockIdx.y * 256;
    const int Ku2 = RANK / 2;

    if (tid < 256) cs[tid] = dB[bn + tid] * VERA_SCALE;

    const int rowA = warp_m * 32 + (lid & 15);
    const uint32_t pA0 = (uint32_t)(rowA * 128), pA1 = pA0 + 2048;
    const uint32_t kbA = (uint32_t)((lid >> 4) * 16);
    const uint32_t xA  = (uint32_t)((rowA & 7) << 4);
    const int rowB = warp_n * 64 + ((lid >> 4) * 8 + (lid & 7));
    const uint32_t pB0 = (uint32_t)(rowB * 128);
    const uint32_t kbB = (uint32_t)(((lid >> 3) & 1) * 16);
    const uint32_t xB  = (uint32_t)((rowB & 7) << 4);

    const int frow = tid >> 3, fc16 = tid & 7;

    float acc[2][8][4];
    #pragma unroll
    for (int i = 0; i < 2; ++i)
        #pragma unroll
        for (int j = 0; j < 8; ++j)
            #pragma unroll
            for (int q = 0; q < 4; ++q) acc[i][j][q] = 0.0f;

    auto fill = [&](uint32_t dstb, int c) {
        const int col = c * 32 + fc16 * 4;
        #pragma unroll
        for (int j = 0; j < 2; ++j) {
            int row = frow + j * 64;
            uint32_t off = sw128((uint32_t)(row * 128 + fc16 * 16));
            cpa16(dstb + off,      Thi_ + (size_t)(bm + row) * Ku2 + col);
            cpa16(dstb + AP + off, Tlo_ + (size_t)(bm + row) * Ku2 + col);
        }
        #pragma unroll
        for (int j = 0; j < 4; ++j) {
            int row = frow + j * 64;
            uint32_t off = sw128((uint32_t)(row * 128 + fc16 * 16));
            cpa16(dstb + 2 * AP + off,      Bhi_ + (size_t)(bn + row) * Ku2 + col);
            cpa16(dstb + 2 * AP + BP + off, Blo_ + (size_t)(bn + row) * Ku2 + col);
        }
    };

    fill(sb, 0);
    CP_COMMIT(); CP_WAIT0();
    __syncthreads();

    #pragma unroll
    for (int ch = 0; ch < 4; ++ch) {
        const uint32_t base = sb + (uint32_t)((ch & 1) * STAGE);
        if (ch < 3) { fill(sb + (uint32_t)(((ch & 1) ^ 1) * STAGE), ch + 1); CP_COMMIT(); }

        #pragma unroll
        for (int s = 0; s < 4; ++s) {
            const uint32_t aoff = ((uint32_t)(s * 32) + kbA) ^ xA;
            const uint32_t boff = ((uint32_t)(s * 32) + kbB) ^ xB;
            uint32_t ah[2][4], al[2][4];
            ldsm4(ah[0], base + pA0 + aoff);
            ldsm4(ah[1], base + pA1 + aoff);
            ldsm4(al[0], base + AP + pA0 + aoff);
            ldsm4(al[1], base + AP + pA1 + aoff);
            #pragma unroll
            for (int g = 0; g < 2; ++g) {
                uint32_t bh[2][4], bl[2][4];
                const uint32_t nb = base + 2 * AP + pB0 + boff + (uint32_t)(g * 4096);
                ldsm4(bh[0], nb);
                ldsm4(bh[1], nb + 2048);
                ldsm4(bl[0], nb + BP);
                ldsm4(bl[1], nb + BP + 2048);
                #pragma unroll
                for (int np = 0; np < 2; ++np)
                    #pragma unroll
                    for (int mi = 0; mi < 2; ++mi) {
                        const int j = (g * 2 + np) * 2;
                        mma_bf16(acc[mi][j],     ah[mi], bh[np][0], bh[np][1]);
                        mma_bf16(acc[mi][j + 1], ah[mi], bh[np][2], bh[np][3]);
                    }
                #pragma unroll
                for (int np = 0; np < 2; ++np)
                    #pragma unroll
                    for (int mi = 0; mi < 2; ++mi) {
                        const int j = (g * 2 + np) * 2;
                        mma_bf16(acc[mi][j],     ah[mi], bl[np][0], bl[np][1]);
                        mma_bf16(acc[mi][j + 1], ah[mi], bl[np][2], bl[np][3]);
                    }
                #pragma unroll
                for (int np = 0; np < 2; ++np)
                    #pragma unroll
                    for (int mi = 0; mi < 2; ++mi) {
                        const int j = (g * 2 + np) * 2;
                        mma_bf16(acc[mi][j],     al[mi], bh[np][0], bh[np][1]);
                        mma_bf16(acc[mi][j + 1], al[mi], bh[np][2], bh[np][3]);
                    }
            }
        }
        CP_WAIT0();
        __syncthreads();
    }

    const int mrow0 = bm + warp_m * 32 + (lid >> 2);
    const int nc0   = warp_n * 64 + (lid & 3) * 2;
    #pragma unroll
    for (int mi = 0; mi < 2; ++mi) {
        #pragma unroll
        for (int nj = 0; nj < 8; ++nj) {
            const int n = nc0 + nj * 8;
            const float s0 = cs[n], s1 = cs[n + 1];
            float2 v0, v1;
            v0.x = acc[mi][nj][0] * s0; v0.y = acc[mi][nj][1] * s1;
            v1.x = acc[mi][nj][2] * s0; v1.y = acc[mi][nj][3] * s1;
            const int m0 = mrow0 + mi * 16;
            *reinterpret_cast<float2*>(Out + (size_t)m0 * N_OUT + bn + n) = v0;
            *reinterpret_cast<float2*>(Out + (size_t)(m0 + 8) * N_OUT + bn + n) = v1;
        }
    }
}

extern "C" void kernel_launch(void* const* d_in, const int* in_sizes, int n_in,
                              void* d_out, int out_size)
{
    const float* x   = (const float*)d_in[0];  // [8192][4096]
    const float* A   = (const float*)d_in[1];  // [256][4096]
    const float* B   = (const float*)d_in[2];  // [4096][256]
    const float* d_A = (const float*)d_in[3];  // [256]
    const float* d_B = (const float*)d_in[4];  // [4096]
    float* out = (float*)d_out;                // [8192][4096]

    uint32_t *Ahi, *Alo, *Bhi, *Blo, *thi, *tlo;
    float* part;
    cudaGetSymbolAddress((void**)&Ahi, g_Ahi);
    cudaGetSymbolAddress((void**)&Alo, g_Alo);
    cudaGetSymbolAddress((void**)&Bhi, g_Bhi);
    cudaGetSymbolAddress((void**)&Blo, g_Blo);
    cudaGetSymbolAddress((void**)&thi, g_thi);
    cudaGetSymbolAddress((void**)&tlo, g_tlo);
    cudaGetSymbolAddress((void**)&part, g_p);

    constexpr int SMEM1 = 2 * 17408 + 2 * 8192 + 2 * 65536;   // 182272
    constexpr int SMEM2 = 2 * (2 * 16384 + 2 * 32768) + 1024; // 197632
    cudaFuncSetAttribute(vera_g1, cudaFuncAttributeMaxDynamicSharedMemorySize, SMEM1);
    cudaFuncSetAttribute(vera_g2, cudaFuncAttributeMaxDynamicSharedMemorySize, SMEM2);

    // pre-split A and B (small)
    {
        int n4 = RANK * K_IN / 4;
        split_kernel<<<n4 / 256, 256>>>((const float4*)A, Ahi, Alo, n4);
        int n4b = N_OUT * RANK / 4;
        split_kernel<<<n4b / 256, 256>>>((const float4*)B, Bhi, Blo, n4b);
    }
    // GEMM1 (fp32 X staged in-kernel; split-K=2): partials
    {
        dim3 grid(M_TOT / 64, 2);   // 256 CTAs
        vera_g1<<<grid, 256, SMEM1>>>(x, Ahi, Alo, part);
    }
    // combine + d_A scale + split t
    {
        int n4 = M_TOT * RANK / 4;
        combine_kernel<<<n4 / 256, 256>>>(part, part + (size_t)M_TOT * RANK,
                                          d_A, thi, tlo, n4);
    }
    // GEMM2
    {
        dim3 grid(M_TOT / 128, N_OUT / 256);  // 64 x 16
        vera_g2<<<grid, 512, SMEM2>>>(thi, tlo, Bhi, Blo, d_B, out);
    }
}

// round 16
// speedup vs baseline: 1.5005x; 1.5005x over previous
#include <cuda_runtime.h>
#include <cuda_bf16.h>
#include <cstdint>

#define M_TOT   8192
#define K_IN    4096
#define RANK    256
#define N_OUT   4096
#define VERA_SCALE (32.0f / 256.0f)

// pre-split bf16 hi/lo planes (packed 2 elems per uint32, row-major)
__device__ uint32_t g_Ahi[(size_t)RANK * K_IN / 2];
__device__ uint32_t g_Alo[(size_t)RANK * K_IN / 2];
__device__ uint32_t g_Bhi[(size_t)N_OUT * RANK / 2];
__device__ uint32_t g_Blo[(size_t)N_OUT * RANK / 2];
// split-K partials for GEMM1 and the split intermediate t
__device__ float    g_p[2][(size_t)M_TOT * RANK];
__device__ uint32_t g_thi[(size_t)M_TOT * RANK / 2];
__device__ uint32_t g_tlo[(size_t)M_TOT * RANK / 2];

// ------------- helpers -------------
__device__ __forceinline__ uint32_t smem_u32(const void* p) {
    uint32_t a;
    asm("{ .reg .u64 t; cvta.to.shared.u64 t, %1; cvt.u32.u64 %0, t; }" : "=r"(a) : "l"(p));
    return a;
}
__device__ __forceinline__ void ldsm4(uint32_t r[4], uint32_t addr) {
    asm volatile("ldmatrix.sync.aligned.m8n8.x4.shared.b16 {%0,%1,%2,%3}, [%4];"
                 : "=r"(r[0]), "=r"(r[1]), "=r"(r[2]), "=r"(r[3]) : "r"(addr));
}
__device__ __forceinline__ void mma_bf16(float c[4], const uint32_t a[4],
                                         uint32_t b0, uint32_t b1) {
    asm volatile(
        "mma.sync.aligned.m16n8k16.row.col.f32.bf16.bf16.f32 "
        "{%0,%1,%2,%3}, {%4,%5,%6,%7}, {%8,%9}, {%0,%1,%2,%3};"
        : "+f"(c[0]), "+f"(c[1]), "+f"(c[2]), "+f"(c[3])
        : "r"(a[0]), "r"(a[1]), "r"(a[2]), "r"(a[3]), "r"(b0), "r"(b1));
}
__device__ __forceinline__ uint32_t sw128(uint32_t b) {
    return b ^ ((b >> 3) & 0x70);
}
__device__ __forceinline__ void split2(float a, float b, uint32_t& hi, uint32_t& lo) {
    uint32_t ua = __float_as_uint(a), ub = __float_as_uint(b);
    hi = __byte_perm(ua, ub, 0x7632);
    float fa = __uint_as_float(ua & 0xFFFF0000u);
    float fb = __uint_as_float(ub & 0xFFFF0000u);
    float la = a - fa, lb = b - fb;
    asm("cvt.rn.bf16x2.f32 %0, %1, %2;" : "=r"(lo) : "f"(lb), "f"(la));
}
__device__ __forceinline__ void cpa16(uint32_t dst, const void* src) {
    asm volatile("cp.async.cg.shared.global [%0], [%1], 16;" :: "r"(dst), "l"(src));
}
#define CP_COMMIT() asm volatile("cp.async.commit_group;" ::: "memory")
#define CP_WAIT0()  asm volatile("cp.async.wait_group 0;" ::: "memory")

// one-shot pre-split: fp32 matrix -> planar packed-bf16 hi/lo (A and B only)
__global__ void split_kernel(const float4* __restrict__ in, uint32_t* __restrict__ hi,
                             uint32_t* __restrict__ lo, int n4) {
    int i = blockIdx.x * blockDim.x + threadIdx.x;
    if (i < n4) {
        float4 v = in[i];
        uint32_t h0, l0, h1, l1;
        split2(v.x, v.y, h0, l0);
        split2(v.z, v.w, h1, l1);
        hi[2 * i] = h0; hi[2 * i + 1] = h1;
        lo[2 * i] = l0; lo[2 * i + 1] = l1;
    }
}

// combine split-K partials, scale by d_A, emit split hi/lo t
__global__ void combine_kernel(const float* __restrict__ p0, const float* __restrict__ p1,
                               const float* __restrict__ dA,
                               uint32_t* __restrict__ thi, uint32_t* __restrict__ tlo,
                               int n4) {
    int i = blockIdx.x * blockDim.x + threadIdx.x;
    if (i < n4) {
        float4 a = reinterpret_cast<const float4*>(p0)[i];
        float4 b = reinterpret_cast<const float4*>(p1)[i];
        int col = (i * 4) & (RANK - 1);
        float4 s = *reinterpret_cast<const float4*>(dA + col);
        uint32_t h, l;
        split2((a.x + b.x) * s.x, (a.y + b.y) * s.y, h, l);
        thi[2 * i] = h; tlo[2 * i] = l;
        split2((a.z + b.z) * s.z, (a.w + b.w) * s.w, h, l);
        thi[2 * i + 1] = h; tlo[2 * i + 1] = l;
    }
}

// ============ GEMM1: partial = X @ A^T (split-K=2) ============
// CTA 128(m) x 256(n=RANK), grid (64 m-tiles, 2 splits) = 128 CTAs.
// 512 threads = 16 warps (4m x 4n), warp tile 32x64. K=2048/split in 32 chunks
// of 64. X: fp32, interleaved register-path producer (LDG before MMA s-step,
// split2+STS after — R6/R7 proven pattern). A: pre-split bf16 via cp.async.
__global__ __launch_bounds__(512, 1)
void vera_g1(const float* __restrict__ X,
             const uint32_t* __restrict__ Ahi_, const uint32_t* __restrict__ Alo_,
             float* __restrict__ Part)
{
    extern __shared__ char smem[];
    constexpr int XP = 16384;                 // one X bf16 plane (128 rows x 128B)
    constexpr int APLANE = 32768;             // one A bf16 plane (256 rows x 128B)
    constexpr int AOFF = 2 * XP;              // 32768
    constexpr int STAGE = 2 * XP + 2 * APLANE;  // 98304
    constexpr int NC = 32;
    const uint32_t sb = smem_u32(smem);

    const int tid = threadIdx.x, wid = tid >> 5, lid = tid & 31;
    const int bm = blockIdx.x * 128;
    const int split = blockIdx.y;
    const int koff_u32 = split * 1024;        // u32 col offset into A planes
    const int koff_el  = split * 2048;        // element offset into X
    const int Ku2 = K_IN / 2;
    float* Out = Part + (size_t)split * M_TOT * RANK;

    // consumer addressing (R11 core)
    const int warp_m = wid & 3, warp_n = wid >> 2;
    const int rowA = warp_m * 32 + (lid & 15);
    const uint32_t pA0 = (uint32_t)(rowA * 128), pA1 = pA0 + 2048;
    const uint32_t kbA = (uint32_t)((lid >> 4) * 16);
    const uint32_t xA  = (uint32_t)((rowA & 7) << 4);
    const int rowB = warp_n * 64 + ((lid >> 4) * 8 + (lid & 7));
    const uint32_t pB0 = (uint32_t)(rowB * 128);
    const uint32_t kbB = (uint32_t)(((lid >> 3) & 1) * 16);
    const uint32_t xB  = (uint32_t)((rowB & 7) << 4);

    // producer addressing: thread -> X row (tid>>2), 4-float col block (tid&3)
    const int prow = tid >> 2;
    const int pc4  = (tid & 3) * 4;
    const float* Xrow = X + (size_t)(bm + prow) * K_IN + koff_el;

    // A-side cp.async mapping: 512 threads, row = tid>>3 (+ j*64), granule tid&7
    const int frow = tid >> 3, fc16 = tid & 7;

    float acc[2][8][4];
    #pragma unroll
    for (int i = 0; i < 2; ++i)
        #pragma unroll
        for (int j = 0; j < 8; ++j)
            #pragma unroll
            for (int q = 0; q < 4; ++q) acc[i][j][q] = 0.0f;

    auto fillA = [&](uint32_t dstb, int ch) {
        const int col = koff_u32 + ch * 32 + fc16 * 4;
        #pragma unroll
        for (int j = 0; j < 4; ++j) {
            int row = frow + j * 64;
            uint32_t off = sw128((uint32_t)(row * 128 + fc16 * 16));
            cpa16(dstb + AOFF + off,          Ahi_ + (size_t)row * Ku2 + col);
            cpa16(dstb + AOFF + APLANE + off, Alo_ + (size_t)row * Ku2 + col);
        }
    };

    // prologue: stage 0 — X via register path, A via cp.async
    fillA(sb, 0);
    CP_COMMIT();
    #pragma unroll
    for (int s = 0; s < 4; ++s) {
        float4 v = *reinterpret_cast<const float4*>(Xrow + s * 16 + pc4);
        uint32_t h0, l0, h1, l1;
        split2(v.x, v.y, h0, l0);
        split2(v.z, v.w, h1, l1);
        uint32_t off = sw128((uint32_t)(prow * 128 + (s * 16 + pc4) * 2));
        *reinterpret_cast<uint2*>(smem + off)      = make_uint2(h0, h1);
        *reinterpret_cast<uint2*>(smem + XP + off) = make_uint2(l0, l1);
    }
    CP_WAIT0();
    __syncthreads();

    for (int ch = 0; ch < NC; ++ch) {
        const uint32_t base = sb + (uint32_t)((ch & 1) * STAGE);
        const uint32_t dstb = sb + (uint32_t)(((ch & 1) ^ 1) * STAGE);
        char* dstc = smem + ((ch & 1) ^ 1) * STAGE;
        const bool more = (ch + 1 < NC);
        const float* Xn = Xrow + (ch + 1) * 64;

        if (more) { fillA(dstb, ch + 1); CP_COMMIT(); }

        #pragma unroll
        for (int s = 0; s < 4; ++s) {
            // issue next-chunk X LDG (consumed after the MMA block)
            float4 xv;
            if (more) xv = *reinterpret_cast<const float4*>(Xn + s * 16 + pc4);

            const uint32_t aoff = ((uint32_t)(s * 32) + kbA) ^ xA;
            const uint32_t boff = ((uint32_t)(s * 32) + kbB) ^ xB;
            uint32_t ah[2][4], al[2][4];
            ldsm4(ah[0], base + pA0 + aoff);
            ldsm4(ah[1], base + pA1 + aoff);
            ldsm4(al[0], base + XP + pA0 + aoff);
            ldsm4(al[1], base + XP + pA1 + aoff);
            #pragma unroll
            for (int g = 0; g < 2; ++g) {
                uint32_t bh[2][4], bl[2][4];
                const uint32_t nb = base + AOFF + pB0 + boff + (uint32_t)(g * 4096);
                ldsm4(bh[0], nb);
                ldsm4(bh[1], nb + 2048);
                ldsm4(bl[0], nb + APLANE);
                ldsm4(bl[1], nb + APLANE + 2048);
                #pragma unroll
                for (int np = 0; np < 2; ++np)
                    #pragma unroll
                    for (int mi = 0; mi < 2; ++mi) {
                        const int j = (g * 2 + np) * 2;
                        mma_bf16(acc[mi][j],     ah[mi], bh[np][0], bh[np][1]);
                        mma_bf16(acc[mi][j + 1], ah[mi], bh[np][2], bh[np][3]);
                    }
                #pragma unroll
                for (int np = 0; np < 2; ++np)
                    #pragma unroll
                    for (int mi = 0; mi < 2; ++mi) {
                        const int j = (g * 2 + np) * 2;
                        mma_bf16(acc[mi][j],     ah[mi], bl[np][0], bl[np][1]);
                        mma_bf16(acc[mi][j + 1], ah[mi], bl[np][2], bl[np][3]);
                    }
                #pragma unroll
                for (int np = 0; np < 2; ++np)
                    #pragma unroll
                    for (int mi = 0; mi < 2; ++mi) {
                        const int j = (g * 2 + np) * 2;
                        mma_bf16(acc[mi][j],     al[mi], bh[np][0], bh[np][1]);
                        mma_bf16(acc[mi][j + 1], al[mi], bh[np][2], bh[np][3]);
                    }
            }

            // consume the LDG: split + STS into the other stage
            if (more) {
                uint32_t h0, l0, h1, l1;
                split2(xv.x, xv.y, h0, l0);
                split2(xv.z, xv.w, h1, l1);
                uint32_t off = sw128((uint32_t)(prow * 128 + (s * 16 + pc4) * 2));
                *reinterpret_cast<uint2*>(dstc + off)      = make_uint2(h0, h1);
                *reinterpret_cast<uint2*>(dstc + XP + off) = make_uint2(l0, l1);
            }
        }
        CP_WAIT0();
        __syncthreads();
    }

    // epilogue: raw fp32 partials (d_A applied in combine)
    const int mrow0 = bm + warp_m * 32 + (lid >> 2);
    const int nc0   = warp_n * 64 + (lid & 3) * 2;
    #pragma unroll
    for (int mi = 0; mi < 2; ++mi) {
        #pragma unroll
        for (int nj = 0; nj < 8; ++nj) {
            const int n = nc0 + nj * 8;
            const int m0 = mrow0 + mi * 16;
            *reinterpret_cast<float2*>(Out + (size_t)m0 * RANK + n) =
                make_float2(acc[mi][nj][0], acc[mi][nj][1]);
            *reinterpret_cast<float2*>(Out + (size_t)(m0 + 8) * RANK + n) =
                make_float2(acc[mi][nj][2], acc[mi][nj][3]);
        }
    }
}

// ============ GEMM2 (verbatim R11/R14 engine, measured 130us) ============
__global__ __launch_bounds__(512, 1)
void vera_g2(const uint32_t* __restrict__ Thi_, const uint32_t* __restrict__ Tlo_,
             const uint32_t* __restrict__ Bhi_, const uint32_t* __restrict__ Blo_,
             const float* __restrict__ dB, float* __restrict__ Out)
{
    extern __shared__ char smem[];
    constexpr int AP = 16384, BP = 32768;
    constexpr int STAGE = 2 * AP + 2 * BP;   // 96KB
    float* cs = reinterpret_cast<float*>(smem + 2 * STAGE);
    const uint32_t sb = smem_u32(smem);

    const int tid = threadIdx.x, wid = tid >> 5, lid = tid & 31;
    const int warp_m = wid & 3, warp_n = wid >> 2;
    const int bm = blockIdx.x * 128, bn = blockIdx.y * 256;
    const int Ku2 = RANK / 2;

    if (tid < 256) cs[tid] = dB[bn + tid] * VERA_SCALE;

    const int rowA = warp_m * 32 + (lid & 15);
    const uint32_t pA0 = (uint32_t)(rowA * 128), pA1 = pA0 + 2048;
    const uint32_t kbA = (uint32_t)((lid >> 4) * 16);
    const uint32_t xA  = (uint32_t)((rowA & 7) << 4);
    const int rowB = warp_n * 64 + ((lid >> 4) * 8 + (lid & 7));
    const uint32_t pB0 = (uint32_t)(rowB * 128);
    const uint32_t kbB = (uint32_t)(((lid >> 3) & 1) * 16);
    const uint32_t xB  = (uint32_t)((rowB & 7) << 4);

    const int frow = tid >> 3, fc16 = tid & 7;

    float acc[2][8][4];
    #pragma unroll
    for (int i = 0; i < 2; ++i)
        #pragma unroll
        for (int j = 0; j < 8; ++j)
            #pragma unroll
            for (int q = 0; q < 4; ++q) acc[i][j][q] = 0.0f;

    auto fill = [&](uint32_t dstb, int c) {
        const int col = c * 32 + fc16 * 4;
        #pragma unroll
        for (int j = 0; j < 2; ++j) {
            int row = frow + j * 64;
            uint32_t off = sw128((uint32_t)(row * 128 + fc16 * 16));
            cpa16(dstb + off,      Thi_ + (size_t)(bm + row) * Ku2 + col);
            cpa16(dstb + AP + off, Tlo_ + (size_t)(bm + row) * Ku2 + col);
        }
        #pragma unroll
        for (int j = 0; j < 4; ++j) {
            int row = frow + j * 64;
            uint32_t off = sw128((uint32_t)(row * 128 + fc16 * 16));
            cpa16(dstb + 2 * AP + off,      Bhi_ + (size_t)(bn + row) * Ku2 + col);
            cpa16(dstb + 2 * AP + BP + off, Blo_ + (size_t)(bn + row) * Ku2 + col);
        }
    };

    fill(sb, 0);
    CP_COMMIT(); CP_WAIT0();
    __syncthreads();

    #pragma unroll
    for (int ch = 0; ch < 4; ++ch) {
        const uint32_t base = sb + (uint32_t)((ch & 1) * STAGE);
        if (ch < 3) { fill(sb + (uint32_t)(((ch & 1) ^ 1) * STAGE), ch + 1); CP_COMMIT(); }

        #pragma unroll
        for (int s = 0; s < 4; ++s) {
            const uint32_t aoff = ((uint32_t)(s * 32) + kbA) ^ xA;
            const uint32_t boff = ((uint32_t)(s * 32) + kbB) ^ xB;
            uint32_t ah[2][4], al[2][4];
            ldsm4(ah[0], base + pA0 + aoff);
            ldsm4(ah[1], base + pA1 + aoff);
            ldsm4(al[0], base + AP + pA0 + aoff);
            ldsm4(al[1], base + AP + pA1 + aoff);
            #pragma unroll
            for (int g = 0; g < 2; ++g) {
                uint32_t bh[2][4], bl[2][4];
                const uint32_t nb = base + 2 * AP + pB0 + boff + (uint32_t)(g * 4096);
                ldsm4(bh[0], nb);
                ldsm4(bh[1], nb + 2048);
                ldsm4(bl[0], nb + BP);
                ldsm4(bl[1], nb + BP + 2048);
                #pragma unroll
                for (int np = 0; np < 2; ++np)
                    #pragma unroll
                    for (int mi = 0; mi < 2; ++mi) {
                        const int j = (g * 2 + np) * 2;
                        mma_bf16(acc[mi][j],     ah[mi], bh[np][0], bh[np][1]);
                        mma_bf16(acc[mi][j + 1], ah[mi], bh[np][2], bh[np][3]);
                    }
                #pragma unroll
                for (int np = 0; np < 2; ++np)
                    #pragma unroll
                    for (int mi = 0; mi < 2; ++mi) {
                        const int j = (g * 2 + np) * 2;
                        mma_bf16(acc[mi][j],     ah[mi], bl[np][0], bl[np][1]);
                        mma_bf16(acc[mi][j + 1], ah[mi], bl[np][2], bl[np][3]);
                    }
                #pragma unroll
                for (int np = 0; np < 2; ++np)
                    #pragma unroll
                    for (int mi = 0; mi < 2; ++mi) {
                        const int j = (g * 2 + np) * 2;
                        mma_bf16(acc[mi][j],     al[mi], bh[np][0], bh[np][1]);
                        mma_bf16(acc[mi][j + 1], al[mi], bh[np][2], bh[np][3]);
                    }
            }
        }
        CP_WAIT0();
        __syncthreads();
    }

    const int mrow0 = bm + warp_m * 32 + (lid >> 2);
    const int nc0   = warp_n * 64 + (lid & 3) * 2;
    #pragma unroll
    for (int mi = 0; mi < 2; ++mi) {
        #pragma unroll
        for (int nj = 0; nj < 8; ++nj) {
            const int n = nc0 + nj * 8;
            const float s0 = cs[n], s1 = cs[n + 1];
            float2 v0, v1;
            v0.x = acc[mi][nj][0] * s0; v0.y = acc[mi][nj][1] * s1;
            v1.x = acc[mi][nj][2] * s0; v1.y = acc[mi][nj][3] * s1;
            const int m0 = mrow0 + mi * 16;
            *reinterpret_cast<float2*>(Out + (size_t)m0 * N_OUT + bn + n) = v0;
            *reinterpret_cast<float2*>(Out + (size_t)(m0 + 8) * N_OUT + bn + n) = v1;
        }
    }
}

extern "C" void kernel_launch(void* const* d_in, const int* in_sizes, int n_in,
                              void* d_out, int out_size)
{
    const float* x   = (const float*)d_in[0];  // [8192][4096]
    const float* A   = (const float*)d_in[1];  // [256][4096]
    const float* B   = (const float*)d_in[2];  // [4096][256]
    const float* d_A = (const float*)d_in[3];  // [256]
    const float* d_B = (const float*)d_in[4];  // [4096]
    float* out = (float*)d_out;                // [8192][4096]

    uint32_t *Ahi, *Alo, *Bhi, *Blo, *thi, *tlo;
    float* part;
    cudaGetSymbolAddress((void**)&Ahi, g_Ahi);
    cudaGetSymbolAddress((void**)&Alo, g_Alo);
    cudaGetSymbolAddress((void**)&Bhi, g_Bhi);
    cudaGetSymbolAddress((void**)&Blo, g_Blo);
    cudaGetSymbolAddress((void**)&thi, g_thi);
    cudaGetSymbolAddress((void**)&tlo, g_tlo);
    cudaGetSymbolAddress((void**)&part, g_p);

    constexpr int SMEM1 = 2 * (2 * 16384 + 2 * 32768);        // 196608
    constexpr int SMEM2 = 2 * (2 * 16384 + 2 * 32768) + 1024; // 197632
    cudaFuncSetAttribute(vera_g1, cudaFuncAttributeMaxDynamicSharedMemorySize, SMEM1);
    cudaFuncSetAttribute(vera_g2, cudaFuncAttributeMaxDynamicSharedMemorySize, SMEM2);

    // pre-split A and B (small; X handled in-kernel by vera_g1)
    {
        int n4 = RANK * K_IN / 4;
        split_kernel<<<n4 / 256, 256>>>((const float4*)A, Ahi, Alo, n4);
        int n4b = N_OUT * RANK / 4;
        split_kernel<<<n4b / 256, 256>>>((const float4*)B, Bhi, Blo, n4b);
    }
    // GEMM1 (interleaved X producer; split-K=2): partials
    {
        dim3 grid(M_TOT / 128, 2);   // 128 CTAs
        vera_g1<<<grid, 512, SMEM1>>>(x, Ahi, Alo, part);
    }
    // combine + d_A scale + split t
    {
        int n4 = M_TOT * RANK / 4;
        combine_kernel<<<n4 / 256, 256>>>(part, part + (size_t)M_TOT * RANK,
                                          d_A, thi, tlo, n4);
    }
    // GEMM2
    {
        dim3 grid(M_TOT / 128, N_OUT / 256);  // 64 x 16
        vera_g2<<<grid, 512, SMEM2>>>(thi, tlo, Bhi, Blo, d_B, out);
    }
}